// round 5
// baseline (speedup 1.0000x reference)
#include <cuda_runtime.h>
#include <cstdint>

#define H       30
#define HP      32
#define BATCHN  16384
#define SEQ     784
#define NC      10

#define WARPS    8          // warps per block; each warp: 4 batch elements
#define EPW      4          // elements per warp
#define THREADS  256
#define TCHUNK   112        // 784 = 7 * 112
#define NCHUNK   7
#define XROW     36         // floats per time-row (36: 16B-aligned rows, conflict-free)

typedef unsigned long long ull;

__device__ __forceinline__ ull ffma2(ull a, ull b, ull c) {
    ull d; asm("fma.rn.f32x2 %0, %1, %2, %3;" : "=l"(d) : "l"(a), "l"(b), "l"(c)); return d;
}
__device__ __forceinline__ ull fadd2(ull a, ull b) {
    ull d; asm("add.rn.f32x2 %0, %1, %2;" : "=l"(d) : "l"(a), "l"(b)); return d;
}
__device__ __forceinline__ ull pack2(float lo, float hi) {
    ull d; asm("mov.b64 %0, {%1, %2};" : "=l"(d) : "f"(lo), "f"(hi)); return d;
}
__device__ __forceinline__ void unpack2(ull v, float& lo, float& hi) {
    asm("mov.b64 {%0, %1}, %2;" : "=f"(lo), "=f"(hi) : "l"(v));
}
__device__ __forceinline__ ull shflx2(ull v, int m) {
    float lo, hi; unpack2(v, lo, hi);
    lo = __shfl_xor_sync(0xFFFFFFFFu, lo, m);
    hi = __shfl_xor_sync(0xFFFFFFFFu, hi, m);
    return pack2(lo, hi);
}
__device__ __forceinline__ float modrelu(float z, float b) {
    float m = fmaxf(fabsf(z) + b, 0.0f);
    unsigned r = __float_as_uint(m) | (__float_as_uint(z) & 0x80000000u);
    return __uint_as_float(r);
}

__global__ __launch_bounds__(THREADS, 2)
void rnn_modrelu_kernel(const float* __restrict__ inputs,   // [B, SEQ]
                        const float* __restrict__ W_ih,     // [H, 1]
                        const float* __restrict__ W_hh,     // [H, H]
                        const float* __restrict__ b_mod,    // [H]
                        const float* __restrict__ W_lin,    // [NC, H]
                        const float* __restrict__ b_lin,    // [NC]
                        float* __restrict__ out)            // [B, NC]
{
    __shared__ __align__(16) float xs[TCHUNK * XROW];
    // h_sh[warp][buf][elem][dim]; dims 30,31 stay 0 forever.
    __shared__ __align__(128) float h_sh[WARPS][2][EPW][HP];

    const int tid  = threadIdx.x;
    const int w    = tid >> 5;
    const int lane = tid & 31;
    const int j    = lane & 15;     // row base
    const int s    = lane >> 4;     // k-half: k in [16s, 16s+16)
    const int d    = j + 16 * s;    // dim this lane FINALIZES
    const bool dok = (d < H);

    const int b0 = (blockIdx.x * WARPS + w) * EPW;   // first batch element

    // Per-lane weights: rows j and j+16, k-half s only, packed along k.
    ull wp0[8], wp1[8];
    const int ks = 16 * s;
    const int r1 = j + 16;
#pragma unroll
    for (int i = 0; i < 8; i++) {
        int k0 = ks + 2 * i, k1 = k0 + 1;
        float a0 = (k0 < H) ? W_hh[j * H + k0] : 0.0f;
        float a1 = (k1 < H) ? W_hh[j * H + k1] : 0.0f;
        wp0[i] = pack2(a0, a1);
        float c0 = (r1 < H && k0 < H) ? W_hh[r1 * H + k0] : 0.0f;
        float c1 = (r1 < H && k1 < H) ? W_hh[r1 * H + k1] : 0.0f;
        wp1[i] = pack2(c0, c1);
    }
    const float wihd = dok ? W_ih[d]  : 0.0f;
    const float bd   = dok ? b_mod[d] : 0.0f;

    // init hidden state buffers to zero
#pragma unroll
    for (int e = 0; e < EPW; e++) {
        h_sh[w][0][e][lane] = 0.0f;
        h_sh[w][1][e][lane] = 0.0f;
    }
    __syncwarp();

    const float* inBase0 = inputs + (size_t)(blockIdx.x * WARPS * EPW) * SEQ;

    for (int ch = 0; ch < NCHUNK; ch++) {
        __syncthreads();
        const float* inBase = inBase0 + ch * TCHUNK;
        // stage 32 rows x TCHUNK steps
        for (int eidx = tid; eidx < WARPS * EPW * TCHUNK; eidx += THREADS) {
            int r = eidx / TCHUNK;           // local batch row 0..31
            int i = eidx - r * TCHUNK;       // time within chunk
            xs[i * XROW + r] = inBase[(size_t)r * SEQ + i];
        }
        __syncthreads();

#pragma unroll 2
        for (int i = 0; i < TCHUNK; i++) {
            const int rb = i & 1;

            // 4 inputs for this warp's elements at step t (one LDS.128 broadcast)
            float4 xv = *(const float4*)&xs[i * XROW + EPW * w];
            const float xe[EPW] = {xv.x, xv.y, xv.z, xv.w};

            float hv[EPW];
#pragma unroll
            for (int e = 0; e < EPW; e++) {
                const ulonglong2* hp =
                    (const ulonglong2*)&h_sh[w][rb][e][ks];
                ulonglong2 q0 = hp[0];
                ulonglong2 q1 = hp[1];
                ulonglong2 q2 = hp[2];
                ulonglong2 q3 = hp[3];

                // partial dots for dims j (P0) and j+16 (P1) over this k-half
                ull P0 = ffma2(wp0[0], q0.x, 0ull);
                ull P1 = ffma2(wp1[0], q0.x, 0ull);
                P0 = ffma2(wp0[1], q0.y, P0);  P1 = ffma2(wp1[1], q0.y, P1);
                P0 = ffma2(wp0[2], q1.x, P0);  P1 = ffma2(wp1[2], q1.x, P1);
                P0 = ffma2(wp0[3], q1.y, P0);  P1 = ffma2(wp1[3], q1.y, P1);
                P0 = ffma2(wp0[4], q2.x, P0);  P1 = ffma2(wp1[4], q2.x, P1);
                P0 = ffma2(wp0[5], q2.y, P0);  P1 = ffma2(wp1[5], q2.y, P1);
                P0 = ffma2(wp0[6], q3.x, P0);  P1 = ffma2(wp1[6], q3.x, P1);
                P0 = ffma2(wp0[7], q3.y, P0);  P1 = ffma2(wp1[7], q3.y, P1);

                // exchange with the other k-half (lane ^ 16); lane d keeps dim d
                const ull send = (s == 0) ? P1 : P0;
                const ull keep = (s == 0) ? P0 : P1;
                const ull Z2   = fadd2(keep, shflx2(send, 16));
                float zl, zh; unpack2(Z2, zl, zh);
                const float z  = fmaf(xe[e], wihd, zl + zh);
                hv[e] = dok ? modrelu(z, bd) : 0.0f;
            }

#pragma unroll
            for (int e = 0; e < EPW; e++)
                h_sh[w][1 - rb][e][d] = hv[e];
            __syncwarp();
        }
    }

    // Final state in buffer 0 (even chunk length).
    if (lane < NC) {
        const int c = lane;
        float wl[H];
#pragma unroll
        for (int k = 0; k < H; k++) wl[k] = W_lin[c * H + k];
        const float bl = b_lin[c];
#pragma unroll
        for (int e = 0; e < EPW; e++) {
            const float* hE = &h_sh[w][0][e][0];
            float sE = bl;
#pragma unroll
            for (int k = 0; k < H; k++) sE = fmaf(wl[k], hE[k], sE);
            out[(size_t)(b0 + e) * NC + c] = sE;
        }
    }
}

extern "C" void kernel_launch(void* const* d_in, const int* in_sizes, int n_in,
                              void* d_out, int out_size) {
    const float* inputs = (const float*)d_in[0];
    const float* W_ih   = (const float*)d_in[1];
    const float* W_hh   = (const float*)d_in[2];
    const float* b_mod  = (const float*)d_in[3];
    const float* W_lin  = (const float*)d_in[4];
    const float* b_lin  = (const float*)d_in[5];
    float* out = (float*)d_out;

    const int nblocks = BATCHN / (EPW * WARPS);   // 512
    rnn_modrelu_kernel<<<nblocks, THREADS>>>(inputs, W_ih, W_hh, b_mod,
                                             W_lin, b_lin, out);
}

// round 7
// speedup vs baseline: 1.0734x; 1.0734x over previous
#include <cuda_runtime.h>
#include <cstdint>

#define H       30
#define HP      32
#define BATCHN  16384
#define SEQ     784
#define NC      10

#define WARPS    8          // warps per block; each warp: 4 batch elements
#define EPW      4
#define THREADS  256
#define TCHUNK   112        // 784 = 7 * 112
#define NCHUNK   7
#define XROW     36         // row stride: 144B, 16B-aligned float4 slots

typedef unsigned long long ull;

__device__ __forceinline__ ull ffma2(ull a, ull b, ull c) {
    ull d; asm("fma.rn.f32x2 %0, %1, %2, %3;" : "=l"(d) : "l"(a), "l"(b), "l"(c)); return d;
}
__device__ __forceinline__ ull pack2(float lo, float hi) {
    ull d; asm("mov.b64 %0, {%1, %2};" : "=l"(d) : "f"(lo), "f"(hi)); return d;
}
__device__ __forceinline__ float hsum2(ull v) {
    float lo, hi;
    asm("mov.b64 {%0, %1}, %2;" : "=f"(lo), "=f"(hi) : "l"(v));
    return lo + hi;
}
__device__ __forceinline__ float modrelu(float z, float b) {
    float m = fmaxf(fabsf(z) + b, 0.0f);
    unsigned r = __float_as_uint(m) | (__float_as_uint(z) & 0x80000000u);
    return __uint_as_float(r);
}

__global__ __launch_bounds__(THREADS, 3)
void rnn_modrelu_kernel(const float* __restrict__ inputs,   // [B, SEQ]
                        const float* __restrict__ W_ih,     // [H, 1]
                        const float* __restrict__ W_hh,     // [H, H]
                        const float* __restrict__ b_mod,    // [H]
                        const float* __restrict__ W_lin,    // [NC, H]
                        const float* __restrict__ b_lin,    // [NC]
                        float* __restrict__ out)            // [B, NC]
{
    __shared__ __align__(16) float xs[TCHUNK * XROW];
    __shared__ __align__(128) float h_sh[WARPS][2][EPW][HP];

    const int tid  = threadIdx.x;
    const int w    = tid >> 5;
    const int lane = tid & 31;
    const int j    = lane & 15;     // row base
    const int s    = lane >> 4;     // k-half: k in [16s, 16s+16)
    const int d    = j + 16 * s;    // dim this lane FINALIZES

    const int b0 = (blockIdx.x * WARPS + w) * EPW;

    // Per-lane weights: rows j and j+16, k-half s only, packed along k.
    ull wp0[8], wp1[8];
    const int ks = 16 * s;
    const int r1 = j + 16;
#pragma unroll
    for (int i = 0; i < 8; i++) {
        int k0 = ks + 2 * i, k1 = k0 + 1;
        float a0 = (k0 < H) ? W_hh[j * H + k0] : 0.0f;
        float a1 = (k1 < H) ? W_hh[j * H + k1] : 0.0f;
        wp0[i] = pack2(a0, a1);
        float c0 = (r1 < H && k0 < H) ? W_hh[r1 * H + k0] : 0.0f;
        float c1 = (r1 < H && k1 < H) ? W_hh[r1 * H + k1] : 0.0f;
        wp1[i] = pack2(c0, c1);
    }
    const bool dok = (d < H);
    const float wihd = dok ? W_ih[d]  : 0.0f;
    const float bd   = dok ? b_mod[d] : 0.0f;

#pragma unroll
    for (int e = 0; e < EPW; e++) {
        h_sh[w][0][e][lane] = 0.0f;
        h_sh[w][1][e][lane] = 0.0f;
    }
    __syncwarp();

    const float* inBase0 = inputs + (size_t)(blockIdx.x * WARPS * EPW) * SEQ;

    for (int ch = 0; ch < NCHUNK; ch++) {
        __syncthreads();
        const float* inBase = inBase0 + ch * TCHUNK;
        for (int eidx = tid; eidx < WARPS * EPW * TCHUNK; eidx += THREADS) {
            int r = eidx / TCHUNK;
            int i = eidx - r * TCHUNK;
            xs[i * XROW + r] = inBase[(size_t)r * SEQ + i];
        }
        __syncthreads();

#pragma unroll 2
        for (int i = 0; i < TCHUNK; i++) {
            const int rb = i & 1;

            // 4 inputs for this warp's elements (one LDS.128 broadcast)
            float4 xv = *(const float4*)&xs[i * XROW + EPW * w];
            const float xe[EPW] = {xv.x, xv.y, xv.z, xv.w};

#pragma unroll
            for (int pr = 0; pr < 2; pr++) {
                const int e0 = 2 * pr, e1 = e0 + 1;
                const ulonglong2* pa = (const ulonglong2*)&h_sh[w][rb][e0][ks];
                const ulonglong2* pb = (const ulonglong2*)&h_sh[w][rb][e1][ks];
                ulonglong2 a0 = pa[0], a1 = pa[1], a2 = pa[2], a3 = pa[3];
                ulonglong2 c0 = pb[0], c1 = pb[1], c2 = pb[2], c3 = pb[3];

                // 4 independent chains: (P0,P1) for e0 and e1
                ull A0 = ffma2(wp0[0], a0.x, 0ull);
                ull A1 = ffma2(wp1[0], a0.x, 0ull);
                ull C0 = ffma2(wp0[0], c0.x, 0ull);
                ull C1 = ffma2(wp1[0], c0.x, 0ull);
                A0 = ffma2(wp0[1], a0.y, A0);  A1 = ffma2(wp1[1], a0.y, A1);
                C0 = ffma2(wp0[1], c0.y, C0);  C1 = ffma2(wp1[1], c0.y, C1);
                A0 = ffma2(wp0[2], a1.x, A0);  A1 = ffma2(wp1[2], a1.x, A1);
                C0 = ffma2(wp0[2], c1.x, C0);  C1 = ffma2(wp1[2], c1.x, C1);
                A0 = ffma2(wp0[3], a1.y, A0);  A1 = ffma2(wp1[3], a1.y, A1);
                C0 = ffma2(wp0[3], c1.y, C0);  C1 = ffma2(wp1[3], c1.y, C1);
                A0 = ffma2(wp0[4], a2.x, A0);  A1 = ffma2(wp1[4], a2.x, A1);
                C0 = ffma2(wp0[4], c2.x, C0);  C1 = ffma2(wp1[4], c2.x, C1);
                A0 = ffma2(wp0[5], a2.y, A0);  A1 = ffma2(wp1[5], a2.y, A1);
                C0 = ffma2(wp0[5], c2.y, C0);  C1 = ffma2(wp1[5], c2.y, C1);
                A0 = ffma2(wp0[6], a3.x, A0);  A1 = ffma2(wp1[6], a3.x, A1);
                C0 = ffma2(wp0[6], c3.x, C0);  C1 = ffma2(wp1[6], c3.x, C1);
                A0 = ffma2(wp0[7], a3.y, A0);  A1 = ffma2(wp1[7], a3.y, A1);
                C0 = ffma2(wp0[7], c3.y, C0);  C1 = ffma2(wp1[7], c3.y, C1);

                // scalar partials: sX0 = dim j partial, sX1 = dim j+16 partial
                const float sA0 = hsum2(A0), sA1 = hsum2(A1);
                const float sC0 = hsum2(C0), sC1 = hsum2(C1);

                // lane finalizes dim d; partner (lane^16) needs our other row.
                const float sndA = s ? sA0 : sA1;   // partial for partner's dim
                const float kpA  = s ? sA1 : sA0;   // partial for our dim
                const float sndC = s ? sC0 : sC1;
                const float kpC  = s ? sC1 : sC0;
                const float rcvA = __shfl_xor_sync(0xFFFFFFFFu, sndA, 16);
                const float rcvC = __shfl_xor_sync(0xFFFFFFFFu, sndC, 16);

                const float zA = fmaf(xe[e0], wihd, kpA + rcvA);
                const float zC = fmaf(xe[e1], wihd, kpC + rcvC);
                // inactive dims (d=30,31): weights/bias are zero -> h stays 0
                h_sh[w][1 - rb][e0][d] = modrelu(zA, bd);
                h_sh[w][1 - rb][e1][d] = modrelu(zC, bd);
            }
            __syncwarp();
        }
    }

    // Final state in buffer 0 (even chunk length).
    if (lane < NC) {
        const int c = lane;
        float wl[H];
#pragma unroll
        for (int k = 0; k < H; k++) wl[k] = W_lin[c * H + k];
        const float bl = b_lin[c];
#pragma unroll
        for (int e = 0; e < EPW; e++) {
            const float* hE = &h_sh[w][0][e][0];
            float sE = bl;
#pragma unroll
            for (int k = 0; k < H; k++) sE = fmaf(wl[k], hE[k], sE);
            out[(size_t)(b0 + e) * NC + c] = sE;
        }
    }
}

extern "C" void kernel_launch(void* const* d_in, const int* in_sizes, int n_in,
                              void* d_out, int out_size) {
    const float* inputs = (const float*)d_in[0];
    const float* W_ih   = (const float*)d_in[1];
    const float* W_hh   = (const float*)d_in[2];
    const float* b_mod  = (const float*)d_in[3];
    const float* W_lin  = (const float*)d_in[4];
    const float* b_lin  = (const float*)d_in[5];
    float* out = (float*)d_out;

    const int nblocks = BATCHN / (EPW * WARPS);   // 512
    rnn_modrelu_kernel<<<nblocks, THREADS>>>(inputs, W_ih, W_hh, b_mod,
                                             W_lin, b_lin, out);
}